// round 1
// baseline (speedup 1.0000x reference)
#include <cuda_runtime.h>
#include <math.h>

#define Bb 2
#define Nn 512
#define Cc 128
#define Hh 8
#define NN (Nn*Nn)

// Scratch (no cudaMalloc allowed): ~100 MB of __device__ globals.
__device__ float g_Ein [Bb*Hh*NN];
__device__ float g_Vin [Bb*Hh*NN];
__device__ float g_Eout[Bb*Hh*NN];
__device__ float g_Vout[Bb*Hh*NN];
__device__ float g_Va  [Bb*2*Hh*NN];

__device__ __forceinline__ float sigmoidf(float x){ return 1.0f/(1.0f + __expf(-x)); }

// ---------------------------------------------------------------------------
// K1: LayerNorm + dual projection (Wv, We: 128->32) + siglin gating.
// 128 threads / block, 64 rows / block. Threads 0..63 do the V projection for
// row t, threads 64..127 do the E projection for row t-64. Weights + e_ln tile
// live in dynamic SMEM (~67 KB).
// ---------------------------------------------------------------------------
__global__ __launch_bounds__(128) void k1_ln_proj_gate(
    const float* __restrict__ e,
    const float* __restrict__ mask,
    const float* __restrict__ ln_w,
    const float* __restrict__ ln_b,
    const float* __restrict__ Wv,
    const float* __restrict__ bv,
    const float* __restrict__ We,
    const float* __restrict__ be)
{
    extern __shared__ float sm[];
    float* sEln = sm;                 // 64*129 = 8256
    float* sWv  = sEln + 64*129;      // 4096
    float* sWe  = sWv + 4096;         // 4096
    float* sBv  = sWe + 4096;         // 32
    float* sBe  = sBv + 32;           // 32
    float* sLnW = sBe + 32;           // 128
    float* sLnB = sLnW + 128;         // 128
    float* sMu  = sLnB + 128;         // 64
    float* sRs  = sMu + 64;           // 64
    float* sPs  = sRs + 64;           // 128
    float* sPq  = sPs + 128;          // 128   -> total 17152 floats

    const int t = threadIdx.x;
    const long g0 = (long)blockIdx.x * 64;

    // Load weights / params into SMEM.
    for (int idx = t; idx < 4096; idx += 128) { sWv[idx] = Wv[idx]; sWe[idx] = We[idx]; }
    if (t < 32) { sBv[t] = bv[t]; sBe[t] = be[t]; }
    sLnW[t] = ln_w[t];
    sLnB[t] = ln_b[t];

    // Load e tile [64 rows x 128 cols], coalesced (one row per iteration).
    for (int r = 0; r < 64; r++)
        sEln[r*129 + t] = e[(g0 + r)*Cc + t];
    __syncthreads();

    // LN stats: two threads per row (halves), then combine.
    {
        int r = t & 63, half = t >> 6;
        float s = 0.f, q = 0.f;
        int c0 = half * 64;
        #pragma unroll 8
        for (int c = c0; c < c0 + 64; c++) { float v = sEln[r*129 + c]; s += v; q += v*v; }
        sPs[t] = s; sPq[t] = q;
    }
    __syncthreads();
    if (t < 64) {
        float s = sPs[t] + sPs[t + 64];
        float q = sPq[t] + sPq[t + 64];
        float mu  = s * (1.f/128.f);
        float var = q * (1.f/128.f) - mu*mu;
        sMu[t] = mu;
        sRs[t] = rsqrtf(var + 1e-5f);
    }
    __syncthreads();

    // Normalize in place (thread t owns column t across all rows).
    for (int r = 0; r < 64; r++) {
        float v = sEln[r*129 + t];
        sEln[r*129 + t] = (v - sMu[r]) * sRs[r] * sLnW[t] + sLnB[t];
    }
    __syncthreads();

    // Projection: 32 accumulators per thread, W read via float4 broadcast.
    const int role = t >> 6;          // 0: V projection, 1: E projection
    const int r    = t & 63;
    const float* W  = role ? sWe : sWv;
    const float* Bp = role ? sBe : sBv;
    float acc[32];
    #pragma unroll
    for (int o = 0; o < 32; o++) acc[o] = Bp[o];

    const float* eRow = sEln + r*129;
    #pragma unroll 4
    for (int c = 0; c < Cc; c++) {
        float x = eRow[c];
        const float4* w4 = (const float4*)(W + c*32);
        #pragma unroll
        for (int o = 0; o < 8; o++) {
            float4 w = w4[o];
            acc[4*o+0] += x * w.x;
            acc[4*o+1] += x * w.y;
            acc[4*o+2] += x * w.z;
            acc[4*o+3] += x * w.w;
        }
    }

    // Gating + scatter to per-(b,h) planes [B*H][N][N], plane[row][col] where
    // (row,col) = original (i,k) of the [B,N,N,*] tensor.
    long g = g0 + r;
    float m = mask[g];
    int b = (int)(g >> 18);
    int i = (int)((g >> 9) & 511);
    int k = (int)(g & 511);
    float* dstIn  = role ? g_Ein  : g_Vin;
    float* dstOut = role ? g_Eout : g_Vout;
    #pragma unroll
    for (int h = 0; h < 8; h++) {
        float vin  = sigmoidf(acc[h]      + m) * acc[8  + h];  // *_in_g, *_in_l
        float vout = sigmoidf(acc[16 + h] + m) * acc[24 + h];  // *_out_g, *_out_l
        long off = ((long)(b*8 + h)*Nn + i)*Nn + k;
        dstIn[off]  = vin;
        dstOut[off] = vout;
    }
}

// ---------------------------------------------------------------------------
// K2: batched 512x512x512 FP32 GEMM per (b,h) plane.
//   KMAJOR=false ("in"):  C[i,j] = sum_k A[i,k]*B[j,k]   (A=E_in, B=V_in, NT)
//   KMAJOR=true  ("out"): C[i,j] = sum_k A[k,i]*B[k,j]   (A=E_out, B=V_out, TN)
// BM=128, BN=64, BK=16, 256 threads (16x16), 8x4 register tile.
// ---------------------------------------------------------------------------
template<bool KMAJOR>
__global__ __launch_bounds__(256) void k2_gemm()
{
    __shared__ float As[16][132];  // row stride 132 floats = 528B (16B aligned)
    __shared__ float Bs[16][68];   // row stride 68 floats  = 272B (16B aligned)

    const int z = blockIdx.z;      // b*8 + h
    const float* A;
    const float* Bm;
    float* C;
    if (KMAJOR) {
        A  = g_Eout + (long)z * NN;
        Bm = g_Vout + (long)z * NN;
        C  = g_Va   + (long)((z >> 3)*16 + 8 + (z & 7)) * NN;
    } else {
        A  = g_Ein + (long)z * NN;
        Bm = g_Vin + (long)z * NN;
        C  = g_Va  + (long)((z >> 3)*16 + (z & 7)) * NN;
    }

    const int t  = threadIdx.x;
    const int tx = t & 15, ty = t >> 4;
    const int i0 = blockIdx.y * 128;
    const int j0 = blockIdx.x * 64;

    float acc[8][4];
    #pragma unroll
    for (int mm = 0; mm < 8; mm++)
        #pragma unroll
        for (int nn = 0; nn < 4; nn++) acc[mm][nn] = 0.f;

    for (int kt = 0; kt < 32; kt++) {
        const int k0 = kt * 16;
        if (KMAJOR) {
            // A[k,i]: coalesced rows of 128 floats -> As[kk][ii].
            #pragma unroll
            for (int u = 0; u < 2; u++) {
                int idx = t + u*256;
                int kk = idx >> 5, ii4 = (idx & 31) * 4;
                float4 v = *(const float4*)(A + (long)(k0 + kk)*Nn + i0 + ii4);
                *(float4*)&As[kk][ii4] = v;
            }
            // B[k,j]: coalesced rows of 64 floats -> Bs[kk][jj].
            {
                int kk = t >> 4, jj4 = (t & 15) * 4;
                float4 v = *(const float4*)(Bm + (long)(k0 + kk)*Nn + j0 + jj4);
                *(float4*)&Bs[kk][jj4] = v;
            }
        } else {
            // A[i,k]: load float4 along k, scatter-transpose into As[kk][ii].
            #pragma unroll
            for (int u = 0; u < 2; u++) {
                int idx = t + u*256;
                int ii = idx >> 2, kk4 = (idx & 3) * 4;
                float4 v = *(const float4*)(A + (long)(i0 + ii)*Nn + k0 + kk4);
                As[kk4+0][ii] = v.x; As[kk4+1][ii] = v.y;
                As[kk4+2][ii] = v.z; As[kk4+3][ii] = v.w;
            }
            {
                int jj = t >> 2, kk4 = (t & 3) * 4;
                float4 v = *(const float4*)(Bm + (long)(j0 + jj)*Nn + k0 + kk4);
                Bs[kk4+0][jj] = v.x; Bs[kk4+1][jj] = v.y;
                Bs[kk4+2][jj] = v.z; Bs[kk4+3][jj] = v.w;
            }
        }
        __syncthreads();

        #pragma unroll
        for (int kk = 0; kk < 16; kk++) {
            float a[8], bfr[4];
            *(float4*)&a[0] = *(const float4*)&As[kk][ty*8];
            *(float4*)&a[4] = *(const float4*)&As[kk][ty*8 + 4];
            *(float4*)&bfr[0] = *(const float4*)&Bs[kk][tx*4];
            #pragma unroll
            for (int mm = 0; mm < 8; mm++)
                #pragma unroll
                for (int nn = 0; nn < 4; nn++)
                    acc[mm][nn] += a[mm] * bfr[nn];
        }
        __syncthreads();
    }

    #pragma unroll
    for (int mm = 0; mm < 8; mm++) {
        float4 v = make_float4(acc[mm][0], acc[mm][1], acc[mm][2], acc[mm][3]);
        *(float4*)(C + (long)(i0 + ty*8 + mm)*Nn + j0 + tx*4) = v;
    }
}

// ---------------------------------------------------------------------------
// K3: O = Va @ Wo + bo ; out = sigmoid(O[:128]) * O[128:].
// One block per (b,i) row of 512 j-positions. Va row strip staged in SMEM,
// Wo columns hoisted into registers (32 per thread). 256 threads:
// c = t&127, j-parity = t>>7.
// ---------------------------------------------------------------------------
__global__ __launch_bounds__(256) void k3_outproj(
    const float* __restrict__ Wo,
    const float* __restrict__ bo,
    float* __restrict__ out)
{
    __shared__ float vas[16*512];   // 32 KB
    const int i = blockIdx.x;
    const int b = blockIdx.y;
    const int t = threadIdx.x;
    const int c  = t & 127;
    const int jp = t >> 7;

    // Cooperative load of Va[b, :, i, :] -> vas[s][j].
    for (int idx = t; idx < 16*512; idx += 256) {
        int s = idx >> 9, j = idx & 511;
        vas[idx] = g_Va[(long)(b*16 + s)*NN + (long)i*Nn + j];
    }

    float wg[16], wl[16];
    #pragma unroll
    for (int s = 0; s < 16; s++) {
        wg[s] = Wo[s*256 + c];
        wl[s] = Wo[s*256 + 128 + c];
    }
    const float bg = bo[c], bl = bo[128 + c];
    __syncthreads();

    float* obase = out + ((long)(b*Nn + i)*Nn) * 128;
    for (int j = jp; j < 512; j += 2) {
        float gacc = bg, lacc = bl;
        #pragma unroll
        for (int s = 0; s < 16; s++) {
            float v = vas[s*512 + j];
            gacc += v * wg[s];
            lacc += v * wl[s];
        }
        obase[(long)j*128 + c] = sigmoidf(gacc) * lacc;
    }
}

// ---------------------------------------------------------------------------
extern "C" void kernel_launch(void* const* d_in, const int* in_sizes, int n_in,
                              void* d_out, int out_size)
{
    const float* e    = (const float*)d_in[0];
    const float* mask = (const float*)d_in[1];
    const float* lnw  = (const float*)d_in[2];
    const float* lnb  = (const float*)d_in[3];
    const float* Wv   = (const float*)d_in[4];
    const float* bv   = (const float*)d_in[5];
    const float* We   = (const float*)d_in[6];
    const float* be   = (const float*)d_in[7];
    const float* Wo   = (const float*)d_in[8];
    const float* bo   = (const float*)d_in[9];
    float* out = (float*)d_out;

    const int SMEM1 = 17152 * 4;  // 68608 B dynamic SMEM for k1
    cudaFuncSetAttribute(k1_ln_proj_gate,
                         cudaFuncAttributeMaxDynamicSharedMemorySize, SMEM1);

    k1_ln_proj_gate<<<8192, 128, SMEM1>>>(e, mask, lnw, lnb, Wv, bv, We, be);

    dim3 g2(Nn/64, Nn/128, Bb*Hh);   // (8, 4, 16)
    k2_gemm<false><<<g2, 256>>>();   // "in"  einsum: E_in  . V_in^T
    k2_gemm<true ><<<g2, 256>>>();   // "out" einsum: E_out^T . V_out

    dim3 g3(Nn, Bb);                 // (512, 2)
    k3_outproj<<<g3, 256>>>(Wo, bo, out);
}

// round 8
// speedup vs baseline: 1.2945x; 1.2945x over previous
#include <cuda_runtime.h>
#include <cuda_bf16.h>
#include <cstdint>
#include <math.h>

#define Bb 2
#define Nn 512
#define Cc 128
#define Hh 8
#define NN (Nn*Nn)

// ---------------------------------------------------------------------------
// Scratch (no cudaMalloc allowed): __device__ globals.
// Packed bf16-split planes: elem = bits(hi) | bits(lo)<<16, hi+lo ~= fp32.
// Layout per array: [16 planes (b*8+h)][512][512].
// ---------------------------------------------------------------------------
__device__ uint32_t g_Ein32 [16*NN];
__device__ uint32_t g_Vin32 [16*NN];
__device__ uint32_t g_Eout32[16*NN];   // native [k][i]
__device__ uint32_t g_Vout32[16*NN];   // native [k][j]
__device__ uint32_t g_EoutT32[16*NN];  // transposed -> [i][k]
__device__ uint32_t g_VoutT32[16*NN];  // transposed -> [j][k]
__device__ float    g_Va[32*NN];       // [b][16 s][i][j], s: 0-7 in, 8-15 out

__device__ __forceinline__ float sigmoidf_(float x){ return 1.0f/(1.0f + __expf(-x)); }

__device__ __forceinline__ uint32_t smem_u32(const void* p) {
    uint32_t a;
    asm("{ .reg .u64 t; cvta.to.shared.u64 t, %1; cvt.u32.u64 %0, t; }" : "=r"(a) : "l"(p));
    return a;
}
__device__ __forceinline__ void ldsm_x4(uint32_t& r0, uint32_t& r1, uint32_t& r2, uint32_t& r3, uint32_t addr) {
    asm volatile("ldmatrix.sync.aligned.m8n8.x4.shared.b16 {%0,%1,%2,%3}, [%4];"
        : "=r"(r0), "=r"(r1), "=r"(r2), "=r"(r3) : "r"(addr));
}
__device__ __forceinline__ void ldsm_x2(uint32_t& r0, uint32_t& r1, uint32_t addr) {
    asm volatile("ldmatrix.sync.aligned.m8n8.x2.shared.b16 {%0,%1}, [%2];"
        : "=r"(r0), "=r"(r1) : "r"(addr));
}
__device__ __forceinline__ void mma_bf16(float* c, const uint32_t* a, const uint32_t* b) {
    asm volatile("mma.sync.aligned.m16n8k16.row.col.f32.bf16.bf16.f32 "
        "{%0,%1,%2,%3}, {%4,%5,%6,%7}, {%8,%9}, {%0,%1,%2,%3};"
        : "+f"(c[0]), "+f"(c[1]), "+f"(c[2]), "+f"(c[3])
        : "r"(a[0]), "r"(a[1]), "r"(a[2]), "r"(a[3]), "r"(b[0]), "r"(b[1]));
}

// ---------------------------------------------------------------------------
// K1: LayerNorm + dual projection + siglin gating; outputs packed bf16-split.
// ---------------------------------------------------------------------------
__global__ __launch_bounds__(128) void k1_ln_proj_gate(
    const float* __restrict__ e,
    const float* __restrict__ mask,
    const float* __restrict__ ln_w,
    const float* __restrict__ ln_b,
    const float* __restrict__ Wv,
    const float* __restrict__ bv,
    const float* __restrict__ We,
    const float* __restrict__ be)
{
    extern __shared__ float sm[];
    float* sEln = sm;                 // 64*129
    float* sWv  = sEln + 64*129;
    float* sWe  = sWv + 4096;
    float* sBv  = sWe + 4096;
    float* sBe  = sBv + 32;
    float* sLnW = sBe + 32;
    float* sLnB = sLnW + 128;
    float* sMu  = sLnB + 128;
    float* sRs  = sMu + 64;
    float* sPs  = sRs + 64;
    float* sPq  = sPs + 128;

    const int t = threadIdx.x;
    const long g0 = (long)blockIdx.x * 64;

    for (int idx = t; idx < 4096; idx += 128) { sWv[idx] = Wv[idx]; sWe[idx] = We[idx]; }
    if (t < 32) { sBv[t] = bv[t]; sBe[t] = be[t]; }
    sLnW[t] = ln_w[t];
    sLnB[t] = ln_b[t];

    for (int r = 0; r < 64; r++)
        sEln[r*129 + t] = e[(g0 + r)*Cc + t];
    __syncthreads();

    {
        int r = t & 63, half = t >> 6;
        float s = 0.f, q = 0.f;
        int c0 = half * 64;
        #pragma unroll 8
        for (int c = c0; c < c0 + 64; c++) { float v = sEln[r*129 + c]; s += v; q += v*v; }
        sPs[t] = s; sPq[t] = q;
    }
    __syncthreads();
    if (t < 64) {
        float s = sPs[t] + sPs[t + 64];
        float q = sPq[t] + sPq[t + 64];
        float mu  = s * (1.f/128.f);
        float var = q * (1.f/128.f) - mu*mu;
        sMu[t] = mu;
        sRs[t] = rsqrtf(var + 1e-5f);
    }
    __syncthreads();

    for (int r = 0; r < 64; r++) {
        float v = sEln[r*129 + t];
        sEln[r*129 + t] = (v - sMu[r]) * sRs[r] * sLnW[t] + sLnB[t];
    }
    __syncthreads();

    const int role = t >> 6;          // 0: V, 1: E
    const int r    = t & 63;
    const float* W  = role ? sWe : sWv;
    const float* Bp = role ? sBe : sBv;
    float acc[32];
    #pragma unroll
    for (int o = 0; o < 32; o++) acc[o] = Bp[o];

    const float* eRow = sEln + r*129;
    #pragma unroll 4
    for (int c = 0; c < Cc; c++) {
        float x = eRow[c];
        const float4* w4 = (const float4*)(W + c*32);
        #pragma unroll
        for (int o = 0; o < 8; o++) {
            float4 w = w4[o];
            acc[4*o+0] += x * w.x;
            acc[4*o+1] += x * w.y;
            acc[4*o+2] += x * w.z;
            acc[4*o+3] += x * w.w;
        }
    }

    long g = g0 + r;
    float m = mask[g];
    int b = (int)(g >> 18);
    int x = (int)((g >> 9) & 511);
    int y = (int)(g & 511);
    uint32_t* dstIn  = role ? g_Ein32  : g_Vin32;
    uint32_t* dstOut = role ? g_Eout32 : g_Vout32;
    #pragma unroll
    for (int h = 0; h < 8; h++) {
        float vin  = sigmoidf_(acc[h]      + m) * acc[8  + h];
        float vout = sigmoidf_(acc[16 + h] + m) * acc[24 + h];
        __nv_bfloat16 h1 = __float2bfloat16_rn(vin);
        __nv_bfloat16 l1 = __float2bfloat16_rn(vin - __bfloat162float(h1));
        __nv_bfloat16 h2 = __float2bfloat16_rn(vout);
        __nv_bfloat16 l2 = __float2bfloat16_rn(vout - __bfloat162float(h2));
        uint32_t p1 = (uint32_t)__bfloat16_as_ushort(h1) | ((uint32_t)__bfloat16_as_ushort(l1) << 16);
        uint32_t p2 = (uint32_t)__bfloat16_as_ushort(h2) | ((uint32_t)__bfloat16_as_ushort(l2) << 16);
        long off = ((long)(b*8 + h)*Nn + x)*Nn + y;
        dstIn[off]  = p1;
        dstOut[off] = p2;
    }
}

// ---------------------------------------------------------------------------
// Transpose 512x512 uint32 planes: Eout/Vout native [k][i] -> [i][k].
// ---------------------------------------------------------------------------
__global__ __launch_bounds__(256) void k_transpose()
{
    __shared__ uint32_t tl[32][33];
    const int z = blockIdx.z;
    const uint32_t* src = (z < 16) ? (g_Eout32 + (long)z*NN) : (g_Vout32 + (long)(z-16)*NN);
    uint32_t*       dst = (z < 16) ? (g_EoutT32 + (long)z*NN) : (g_VoutT32 + (long)(z-16)*NN);
    const int x0 = blockIdx.x * 32;
    const int y0 = blockIdx.y * 32;
    const int tx = threadIdx.x, ty = threadIdx.y;
    #pragma unroll
    for (int rr = 0; rr < 32; rr += 8)
        tl[ty + rr][tx] = src[(long)(x0 + ty + rr)*Nn + y0 + tx];
    __syncthreads();
    #pragma unroll
    for (int rr = 0; rr < 32; rr += 8)
        dst[(long)(y0 + ty + rr)*Nn + x0 + tx] = tl[tx][ty + rr];
}

// ---------------------------------------------------------------------------
// K2: bf16-split GEMM via ldmatrix + mma.sync.m16n8k16 (base-ISA HMMA path).
// CTA tile 128(i) x 128(j), K chunk 64. 8 warps = 2(m) x 4(n); warp tile 64x32.
// D[i,j] = sum_k A[i,k]*B[j,k]; 3 products AhBh + AhBl + AlBh.
// grid (4,4,32): z<16 -> "in" planes; z>=16 -> "out" (transposed) planes.
// ---------------------------------------------------------------------------
#define STRB   144                     // SMEM row stride bytes (72 bf16)
#define TILEB  (128*STRB)              // 18432 B per tile
#define K2_SMEM (4*TILEB)              // Ah, Al, Bh, Bl = 73728 B

__global__ __launch_bounds__(256, 1) void k2_mma(float* __restrict__ Va)
{
    extern __shared__ char smraw[];
    char* smAh = smraw;
    char* smAl = smraw + TILEB;
    char* smBh = smraw + 2*TILEB;
    char* smBl = smraw + 3*TILEB;
    const uint32_t sbAh = smem_u32(smAh);
    const uint32_t sbAl = sbAh + TILEB;
    const uint32_t sbBh = sbAh + 2*TILEB;
    const uint32_t sbBl = sbAh + 3*TILEB;

    const int t = threadIdx.x;
    const int wid = t >> 5, lid = t & 31;
    const int warp_m = wid >> 2;       // 0..1
    const int warp_n = wid & 3;        // 0..3

    const int z = blockIdx.z;
    const uint32_t* A;
    const uint32_t* B;
    float* C;
    if (z < 16) {
        A = g_Ein32 + (long)z*NN;
        B = g_Vin32 + (long)z*NN;
        C = Va + (long)((z >> 3)*16 + (z & 7))*NN;
    } else {
        int p = z - 16;
        A = g_EoutT32 + (long)p*NN;
        B = g_VoutT32 + (long)p*NN;
        C = Va + (long)((p >> 3)*16 + 8 + (p & 7))*NN;
    }
    const int i0 = blockIdx.y * 128;
    const int j0 = blockIdx.x * 128;

    float acc[4][4][4];
    #pragma unroll
    for (int mt = 0; mt < 4; mt++)
        #pragma unroll
        for (int nt = 0; nt < 4; nt++)
            #pragma unroll
            for (int q = 0; q < 4; q++) acc[mt][nt][q] = 0.f;

    // ldmatrix lane address components (constant across chunks)
    const int lrow_a = (lid & 7) + ((lid >> 3) & 1) * 8;   // row within 16-block
    const int lk_a   = (lid >> 4) * 8;                      // 0 or 8 (k offset)
    const int lrow_b = lid & 7;
    const int lk_b   = ((lid >> 3) & 1) * 8;

    for (int kc = 0; kc < 8; kc++) {
        const int k0 = kc * 64;
        // Stage: load packed uint32, unpack into hi/lo bf16 tiles.
        #pragma unroll
        for (int it = 0; it < 8; it++) {
            int idx = it*256 + t;
            int row = idx >> 4, c = idx & 15;        // c: 4 k-elems per uint4
            uint32_t off = (uint32_t)(row*STRB + c*8);
            {
                uint4 v = *(const uint4*)(A + (long)(i0+row)*Nn + k0 + c*4);
                uint2 hi = make_uint2(__byte_perm(v.x, v.y, 0x5410), __byte_perm(v.z, v.w, 0x5410));
                uint2 lo = make_uint2(__byte_perm(v.x, v.y, 0x7632), __byte_perm(v.z, v.w, 0x7632));
                *(uint2*)(smAh + off) = hi;
                *(uint2*)(smAl + off) = lo;
            }
            {
                uint4 v = *(const uint4*)(B + (long)(j0+row)*Nn + k0 + c*4);
                uint2 hi = make_uint2(__byte_perm(v.x, v.y, 0x5410), __byte_perm(v.z, v.w, 0x5410));
                uint2 lo = make_uint2(__byte_perm(v.x, v.y, 0x7632), __byte_perm(v.z, v.w, 0x7632));
                *(uint2*)(smBh + off) = hi;
                *(uint2*)(smBl + off) = lo;
            }
        }
        __syncthreads();

        #pragma unroll
        for (int ks = 0; ks < 4; ks++) {
            uint32_t ah[4][4], al[4][4], bh[4][2], bl[4][2];
            #pragma unroll
            for (int mt = 0; mt < 4; mt++) {
                int row = warp_m*64 + mt*16 + lrow_a;
                uint32_t aoff = (uint32_t)(row*STRB + (ks*16 + lk_a)*2);
                ldsm_x4(ah[mt][0], ah[mt][1], ah[mt][2], ah[mt][3], sbAh + aoff);
                ldsm_x4(al[mt][0], al[mt][1], al[mt][2], al[mt][3], sbAl + aoff);
            }
            #pragma unroll
            for (int nt = 0; nt < 4; nt++) {
                int row = warp_n*32 + nt*8 + lrow_b;
                uint32_t boff = (uint32_t)(row*STRB + (ks*16 + lk_b)*2);
                ldsm_x2(bh[nt][0], bh[nt][1], sbBh + boff);
                ldsm_x2(bl[nt][0], bl[nt][1], sbBl + boff);
            }
            #pragma unroll
            for (int mt = 0; mt < 4; mt++)
                #pragma unroll
                for (int nt = 0; nt < 4; nt++) {
                    mma_bf16(acc[mt][nt], ah[mt], bh[nt]);
                    mma_bf16(acc[mt][nt], ah[mt], bl[nt]);
                    mma_bf16(acc[mt][nt], al[mt], bh[nt]);
                }
        }
        __syncthreads();
    }

    // Epilogue: c0,c1 -> (row, col..col+1); c2,c3 -> (row+8, col..col+1).
    const int rbase = i0 + warp_m*64 + (lid >> 2);
    const int cbase = j0 + warp_n*32 + (lid & 3)*2;
    #pragma unroll
    for (int mt = 0; mt < 4; mt++)
        #pragma unroll
        for (int nt = 0; nt < 4; nt++) {
            int row = rbase + mt*16;
            int col = cbase + nt*8;
            *(float2*)(C + (long)row*Nn + col)       = make_float2(acc[mt][nt][0], acc[mt][nt][1]);
            *(float2*)(C + (long)(row+8)*Nn + col)   = make_float2(acc[mt][nt][2], acc[mt][nt][3]);
        }
}

// ---------------------------------------------------------------------------
// K3: O = Va @ Wo + bo ; out = sigmoid(O[:128]) * O[128:].
// ---------------------------------------------------------------------------
__global__ __launch_bounds__(256) void k3_outproj(
    const float* __restrict__ Wo,
    const float* __restrict__ bo,
    float* __restrict__ out)
{
    __shared__ float vas[512*20];   // 40 KB, [j][20] (16 used, pad 4)
    const int i = blockIdx.x;
    const int b = blockIdx.y;
    const int t = threadIdx.x;
    const int c  = t & 127;
    const int jp = t >> 7;

    for (int idx = t; idx < 16*512; idx += 256) {
        int s = idx >> 9, j = idx & 511;
        vas[j*20 + s] = g_Va[(long)(b*16 + s)*NN + (long)i*Nn + j];
    }

    float wg[16], wl[16];
    #pragma unroll
    for (int s = 0; s < 16; s++) {
        wg[s] = Wo[s*256 + c];
        wl[s] = Wo[s*256 + 128 + c];
    }
    const float bg = bo[c], bl = bo[128 + c];
    __syncthreads();

    float* obase = out + ((long)(b*Nn + i)*Nn) * 128;
    for (int j = jp; j < 512; j += 2) {
        const float4* v4 = (const float4*)(vas + j*20);
        float gacc = bg, lacc = bl;
        #pragma unroll
        for (int q = 0; q < 4; q++) {
            float4 v = v4[q];
            gacc += v.x * wg[4*q+0]; lacc += v.x * wl[4*q+0];
            gacc += v.y * wg[4*q+1]; lacc += v.y * wl[4*q+1];
            gacc += v.z * wg[4*q+2]; lacc += v.z * wl[4*q+2];
            gacc += v.w * wg[4*q+3]; lacc += v.w * wl[4*q+3];
        }
        obase[(long)j*128 + c] = sigmoidf_(gacc) * lacc;
    }
}

// ---------------------------------------------------------------------------
extern "C" void kernel_launch(void* const* d_in, const int* in_sizes, int n_in,
                              void* d_out, int out_size)
{
    const float* e    = (const float*)d_in[0];
    const float* mask = (const float*)d_in[1];
    const float* lnw  = (const float*)d_in[2];
    const float* lnb  = (const float*)d_in[3];
    const float* Wv   = (const float*)d_in[4];
    const float* bv   = (const float*)d_in[5];
    const float* We   = (const float*)d_in[6];
    const float* be   = (const float*)d_in[7];
    const float* Wo   = (const float*)d_in[8];
    const float* bo   = (const float*)d_in[9];
    float* out = (float*)d_out;

    static float* s_va = nullptr;
    if (!s_va) cudaGetSymbolAddress((void**)&s_va, g_Va);

    const int SMEM1 = 17152 * 4;
    cudaFuncSetAttribute(k1_ln_proj_gate,
                         cudaFuncAttributeMaxDynamicSharedMemorySize, SMEM1);
    cudaFuncSetAttribute(k2_mma,
                         cudaFuncAttributeMaxDynamicSharedMemorySize, K2_SMEM);

    k1_ln_proj_gate<<<8192, 128, SMEM1>>>(e, mask, lnw, lnb, Wv, bv, We, be);

    dim3 gt(16, 16, 32);
    k_transpose<<<gt, dim3(32, 8)>>>();

    dim3 g2(4, 4, 32);
    k2_mma<<<g2, 256, K2_SMEM>>>(s_va);

    dim3 g3(Nn, Bb);
    k3_outproj<<<g3, 256>>>(Wo, bo, out);
}

// round 9
// speedup vs baseline: 1.3501x; 1.0430x over previous
#include <cuda_runtime.h>
#include <cuda_bf16.h>
#include <cstdint>
#include <math.h>

#define Bb 2
#define Nn 512
#define Cc 128
#define Hh 8
#define NN (Nn*Nn)

// ---------------------------------------------------------------------------
// Scratch (no cudaMalloc allowed): __device__ globals.
// Packed bf16-split planes: elem = bits(hi) | bits(lo)<<16, hi+lo ~= fp32.
// ---------------------------------------------------------------------------
__device__ uint32_t g_Ein32 [16*NN];
__device__ uint32_t g_Vin32 [16*NN];
__device__ uint32_t g_Eout32[16*NN];   // native [k][i]
__device__ uint32_t g_Vout32[16*NN];   // native [k][j]
__device__ uint32_t g_EoutT32[16*NN];  // transposed -> [i][k]
__device__ uint32_t g_VoutT32[16*NN];  // transposed -> [j][k]
__device__ float    g_Va[32*NN];       // [b][16 s][i][j], s: 0-7 in, 8-15 out

__device__ __forceinline__ float sigmoidf_(float x){ return 1.0f/(1.0f + __expf(-x)); }

__device__ __forceinline__ uint32_t smem_u32(const void* p) {
    uint32_t a;
    asm("{ .reg .u64 t; cvta.to.shared.u64 t, %1; cvt.u32.u64 %0, t; }" : "=r"(a) : "l"(p));
    return a;
}
__device__ __forceinline__ void ldsm_x4(uint32_t& r0, uint32_t& r1, uint32_t& r2, uint32_t& r3, uint32_t addr) {
    asm volatile("ldmatrix.sync.aligned.m8n8.x4.shared.b16 {%0,%1,%2,%3}, [%4];"
        : "=r"(r0), "=r"(r1), "=r"(r2), "=r"(r3) : "r"(addr));
}
__device__ __forceinline__ void ldsm_x2(uint32_t& r0, uint32_t& r1, uint32_t addr) {
    asm volatile("ldmatrix.sync.aligned.m8n8.x2.shared.b16 {%0,%1}, [%2];"
        : "=r"(r0), "=r"(r1) : "r"(addr));
}
__device__ __forceinline__ void mma_bf16(float* c, const uint32_t* a, const uint32_t* b) {
    asm volatile("mma.sync.aligned.m16n8k16.row.col.f32.bf16.bf16.f32 "
        "{%0,%1,%2,%3}, {%4,%5,%6,%7}, {%8,%9}, {%0,%1,%2,%3};"
        : "+f"(c[0]), "+f"(c[1]), "+f"(c[2]), "+f"(c[3])
        : "r"(a[0]), "r"(a[1]), "r"(a[2]), "r"(a[3]), "r"(b[0]), "r"(b[1]));
}
__device__ __forceinline__ void split2(float v, unsigned short& h, unsigned short& l) {
    __nv_bfloat16 hb = __float2bfloat16_rn(v);
    float r = v - __bfloat162float(hb);
    __nv_bfloat16 lb = __float2bfloat16_rn(r);
    h = __bfloat16_as_ushort(hb);
    l = __bfloat16_as_ushort(lb);
}
__device__ __forceinline__ uint32_t packsplit(float v) {
    unsigned short h, l; split2(v, h, l);
    return (uint32_t)h | ((uint32_t)l << 16);
}

// ---------------------------------------------------------------------------
// K1 (tensorized): LN + dual projection on HMMA + siglin gating.
// CTA = 128 rows (same (b,x), y0..y0+127), 256 threads (8 warps x 16 rows).
// GEMM: M=128, N=64 ([Wv|We]), K=128; bf16 split, 3 products.
// ---------------------------------------------------------------------------
#define K1_OFF_E    0            // 128*132*4 = 67584
#define K1_OFF_AH   67584        // 128*136*2 = 34816
#define K1_OFF_AL   102400       // 34816
#define K1_OFF_WH   137216       // 64*136*2 = 17408
#define K1_OFF_WL   154624       // 17408
#define K1_OFF_BIAS 172032       // 64*4
#define K1_OFF_MASK 172288       // 128*4
#define K1_OFF_PS   172800       // 256*4
#define K1_OFF_PQ   173824       // 256*4
#define K1_OFF_MU   174848       // 128*4
#define K1_OFF_RS   175360       // 128*4
#define K1_OFF_LNW  175872       // 128*4
#define K1_OFF_LNB  176384       // 128*4
#define K1_SMEM     176896

__global__ __launch_bounds__(256, 1) void k1_ln_proj_gate(
    const float* __restrict__ e,
    const float* __restrict__ mask,
    const float* __restrict__ ln_w,
    const float* __restrict__ ln_b,
    const float* __restrict__ Wv,
    const float* __restrict__ bv,
    const float* __restrict__ We,
    const float* __restrict__ be)
{
    extern __shared__ char smraw[];
    float*          sE    = (float*)(smraw + K1_OFF_E);     // [128][132]
    unsigned short* sAh   = (unsigned short*)(smraw + K1_OFF_AH);  // [128][136]
    unsigned short* sAl   = (unsigned short*)(smraw + K1_OFF_AL);
    unsigned short* sWh   = (unsigned short*)(smraw + K1_OFF_WH);  // [64][136]
    unsigned short* sWl   = (unsigned short*)(smraw + K1_OFF_WL);
    float*          sBias = (float*)(smraw + K1_OFF_BIAS);
    float*          sMask = (float*)(smraw + K1_OFF_MASK);
    float*          sPs   = (float*)(smraw + K1_OFF_PS);
    float*          sPq   = (float*)(smraw + K1_OFF_PQ);
    float*          sMu   = (float*)(smraw + K1_OFF_MU);
    float*          sRs   = (float*)(smraw + K1_OFF_RS);
    float*          sLnW  = (float*)(smraw + K1_OFF_LNW);
    float*          sLnB  = (float*)(smraw + K1_OFF_LNB);

    const int t   = threadIdx.x;
    const int wid = t >> 5, lid = t & 31;
    const long g0 = (long)blockIdx.x * 128;
    const int b  = (int)(blockIdx.x >> 11);
    const int x  = (int)((blockIdx.x >> 2) & 511);
    const int y0 = (int)((blockIdx.x & 3) * 128);

    // --- Stage weights/params ---
    // W^T split: WT[n][k], n<32 -> Wv col n; n>=32 -> We col n-32.
    for (int idx = t; idx < 8192; idx += 256) {
        int k = idx >> 6, n = idx & 63;
        float w = (n < 32) ? Wv[k*32 + n] : We[k*32 + (n - 32)];
        unsigned short h, l; split2(w, h, l);
        sWh[n*136 + k] = h;
        sWl[n*136 + k] = l;
    }
    if (t < 64)  sBias[t] = (t < 32) ? bv[t] : be[t - 32];
    if (t < 128) { sLnW[t] = ln_w[t]; sLnB[t] = ln_b[t]; sMask[t] = mask[g0 + t]; }

    // --- Stage e tile [128][128] fp32 ---
    for (int it = 0; it < 16; it++) {
        int idx = it*256 + t;
        int row = idx >> 5, c4 = idx & 31;
        float4 v = *(const float4*)(e + (g0 + row)*Cc + c4*4);
        *(float4*)(sE + row*132 + c4*4) = v;
    }
    __syncthreads();

    // --- LN stats: 2 threads per row ---
    {
        int row = t >> 1, half = t & 1;
        float s = 0.f, q = 0.f;
        const float* p = sE + row*132 + half*64;
        #pragma unroll 8
        for (int c = 0; c < 64; c++) { float v = p[c]; s += v; q += v*v; }
        sPs[t] = s; sPq[t] = q;
    }
    __syncthreads();
    if (t < 128) {
        float s = sPs[t*2] + sPs[t*2+1];
        float q = sPq[t*2] + sPq[t*2+1];
        float mu  = s * (1.f/128.f);
        float var = q * (1.f/128.f) - mu*mu;
        sMu[t] = mu;
        sRs[t] = rsqrtf(var + 1e-5f);
    }
    __syncthreads();

    // --- Normalize + bf16 split -> sAh/sAl ---
    {
        int row = t >> 1, half = t & 1;
        float mu = sMu[row], rs = sRs[row];
        #pragma unroll 4
        for (int c = half*64; c < half*64 + 64; c++) {
            float v = (sE[row*132 + c] - mu) * rs * sLnW[c] + sLnB[c];
            unsigned short h, l; split2(v, h, l);
            sAh[row*136 + c] = h;
            sAl[row*136 + c] = l;
        }
    }
    __syncthreads();

    // --- MMA: warp wid rows 16*wid..+15; N=64 (8 nt); K=128 (8 ks); 3 products ---
    const uint32_t sbAh = smem_u32(sAh);
    const uint32_t sbAl = smem_u32(sAl);
    const uint32_t sbWh = smem_u32(sWh);
    const uint32_t sbWl = smem_u32(sWl);
    const int lrow_a = (lid & 7) + ((lid >> 3) & 1) * 8;
    const int lk_a   = (lid >> 4) * 8;
    const int lrow_b = lid & 7;
    const int lk_b   = ((lid >> 3) & 1) * 8;

    float acc[8][4];
    #pragma unroll
    for (int nt = 0; nt < 8; nt++)
        #pragma unroll
        for (int q = 0; q < 4; q++) acc[nt][q] = 0.f;

    #pragma unroll
    for (int ks = 0; ks < 8; ks++) {
        uint32_t ah[4], al[4];
        uint32_t aoff = (uint32_t)((wid*16 + lrow_a)*272 + (ks*16 + lk_a)*2);
        ldsm_x4(ah[0], ah[1], ah[2], ah[3], sbAh + aoff);
        ldsm_x4(al[0], al[1], al[2], al[3], sbAl + aoff);
        #pragma unroll
        for (int nt = 0; nt < 8; nt++) {
            uint32_t bh[2], bl[2];
            uint32_t boff = (uint32_t)((nt*8 + lrow_b)*272 + (ks*16 + lk_b)*2);
            ldsm_x2(bh[0], bh[1], sbWh + boff);
            ldsm_x2(bl[0], bl[1], sbWl + boff);
            mma_bf16(acc[nt], ah, bh);
            mma_bf16(acc[nt], ah, bl);
            mma_bf16(acc[nt], al, bh);
        }
    }

    // --- Gate + scatter ---
    // acc[nt][q]: row = 16*wid + (lid>>2) + (q>=2 ? 8 : 0), col = nt*8 + (lid&3)*2 + (q&1)
    // nt: 0 Vin_g, 1 Vin_l, 2 Vout_g, 3 Vout_l, 4 Ein_g, 5 Ein_l, 6 Eout_g, 7 Eout_l
    #pragma unroll
    for (int q = 0; q < 4; q++) {
        int row = 16*wid + (lid >> 2) + ((q >> 1) * 8);
        int h   = (lid & 3)*2 + (q & 1);
        float m = sMask[row];
        float vin  = sigmoidf_(acc[0][q] + sBias[h]      + m) * (acc[1][q] + sBias[8  + h]);
        float vout = sigmoidf_(acc[2][q] + sBias[16 + h] + m) * (acc[3][q] + sBias[24 + h]);
        float ein  = sigmoidf_(acc[4][q] + sBias[32 + h] + m) * (acc[5][q] + sBias[40 + h]);
        float eout = sigmoidf_(acc[6][q] + sBias[48 + h] + m) * (acc[7][q] + sBias[56 + h]);
        long off = ((long)(b*8 + h)*Nn + x)*Nn + (y0 + row);
        g_Vin32 [off] = packsplit(vin);
        g_Vout32[off] = packsplit(vout);
        g_Ein32 [off] = packsplit(ein);
        g_Eout32[off] = packsplit(eout);
    }
}

// ---------------------------------------------------------------------------
// Transpose 512x512 uint32 planes: Eout/Vout native [k][i] -> [i][k].
// ---------------------------------------------------------------------------
__global__ __launch_bounds__(256) void k_transpose()
{
    __shared__ uint32_t tl[32][33];
    const int z = blockIdx.z;
    const uint32_t* src = (z < 16) ? (g_Eout32 + (long)z*NN) : (g_Vout32 + (long)(z-16)*NN);
    uint32_t*       dst = (z < 16) ? (g_EoutT32 + (long)z*NN) : (g_VoutT32 + (long)(z-16)*NN);
    const int x0 = blockIdx.x * 32;
    const int y0 = blockIdx.y * 32;
    const int tx = threadIdx.x, ty = threadIdx.y;
    #pragma unroll
    for (int rr = 0; rr < 32; rr += 8)
        tl[ty + rr][tx] = src[(long)(x0 + ty + rr)*Nn + y0 + tx];
    __syncthreads();
    #pragma unroll
    for (int rr = 0; rr < 32; rr += 8)
        dst[(long)(y0 + ty + rr)*Nn + x0 + tx] = tl[tx][ty + rr];
}

// ---------------------------------------------------------------------------
// K2: bf16-split GEMM via ldmatrix + mma.sync.m16n8k16 (unchanged, passing).
// ---------------------------------------------------------------------------
#define STRB   144
#define TILEB  (128*STRB)
#define K2_SMEM (4*TILEB)

__global__ __launch_bounds__(256, 1) void k2_mma(float* __restrict__ Va)
{
    extern __shared__ char smraw[];
    char* smAh = smraw;
    char* smAl = smraw + TILEB;
    char* smBh = smraw + 2*TILEB;
    char* smBl = smraw + 3*TILEB;
    const uint32_t sbAh = smem_u32(smAh);
    const uint32_t sbAl = sbAh + TILEB;
    const uint32_t sbBh = sbAh + 2*TILEB;
    const uint32_t sbBl = sbAh + 3*TILEB;

    const int t = threadIdx.x;
    const int wid = t >> 5, lid = t & 31;
    const int warp_m = wid >> 2;
    const int warp_n = wid & 3;

    const int z = blockIdx.z;
    const uint32_t* A;
    const uint32_t* B;
    float* C;
    if (z < 16) {
        A = g_Ein32 + (long)z*NN;
        B = g_Vin32 + (long)z*NN;
        C = Va + (long)((z >> 3)*16 + (z & 7))*NN;
    } else {
        int p = z - 16;
        A = g_EoutT32 + (long)p*NN;
        B = g_VoutT32 + (long)p*NN;
        C = Va + (long)((p >> 3)*16 + 8 + (p & 7))*NN;
    }
    const int i0 = blockIdx.y * 128;
    const int j0 = blockIdx.x * 128;

    float acc[4][4][4];
    #pragma unroll
    for (int mt = 0; mt < 4; mt++)
        #pragma unroll
        for (int nt = 0; nt < 4; nt++)
            #pragma unroll
            for (int q = 0; q < 4; q++) acc[mt][nt][q] = 0.f;

    const int lrow_a = (lid & 7) + ((lid >> 3) & 1) * 8;
    const int lk_a   = (lid >> 4) * 8;
    const int lrow_b = lid & 7;
    const int lk_b   = ((lid >> 3) & 1) * 8;

    for (int kc = 0; kc < 8; kc++) {
        const int k0 = kc * 64;
        #pragma unroll
        for (int it = 0; it < 8; it++) {
            int idx = it*256 + t;
            int row = idx >> 4, c = idx & 15;
            uint32_t off = (uint32_t)(row*STRB + c*8);
            {
                uint4 v = *(const uint4*)(A + (long)(i0+row)*Nn + k0 + c*4);
                uint2 hi = make_uint2(__byte_perm(v.x, v.y, 0x5410), __byte_perm(v.z, v.w, 0x5410));
                uint2 lo = make_uint2(__byte_perm(v.x, v.y, 0x7632), __byte_perm(v.z, v.w, 0x7632));
                *(uint2*)(smAh + off) = hi;
                *(uint2*)(smAl + off) = lo;
            }
            {
                uint4 v = *(const uint4*)(B + (long)(j0+row)*Nn + k0 + c*4);
                uint2 hi = make_uint2(__byte_perm(v.x, v.y, 0x5410), __byte_perm(v.z, v.w, 0x5410));
                uint2 lo = make_uint2(__byte_perm(v.x, v.y, 0x7632), __byte_perm(v.z, v.w, 0x7632));
                *(uint2*)(smBh + off) = hi;
                *(uint2*)(smBl + off) = lo;
            }
        }
        __syncthreads();

        #pragma unroll
        for (int ks = 0; ks < 4; ks++) {
            uint32_t ah[4][4], al[4][4], bh[4][2], bl[4][2];
            #pragma unroll
            for (int mt = 0; mt < 4; mt++) {
                int row = warp_m*64 + mt*16 + lrow_a;
                uint32_t aoff = (uint32_t)(row*STRB + (ks*16 + lk_a)*2);
                ldsm_x4(ah[mt][0], ah[mt][1], ah[mt][2], ah[mt][3], sbAh + aoff);
                ldsm_x4(al[mt][0], al[mt][1], al[mt][2], al[mt][3], sbAl + aoff);
            }
            #pragma unroll
            for (int nt = 0; nt < 4; nt++) {
                int row = warp_n*32 + nt*8 + lrow_b;
                uint32_t boff = (uint32_t)(row*STRB + (ks*16 + lk_b)*2);
                ldsm_x2(bh[nt][0], bh[nt][1], sbBh + boff);
                ldsm_x2(bl[nt][0], bl[nt][1], sbBl + boff);
            }
            #pragma unroll
            for (int mt = 0; mt < 4; mt++)
                #pragma unroll
                for (int nt = 0; nt < 4; nt++) {
                    mma_bf16(acc[mt][nt], ah[mt], bh[nt]);
                    mma_bf16(acc[mt][nt], ah[mt], bl[nt]);
                    mma_bf16(acc[mt][nt], al[mt], bh[nt]);
                }
        }
        __syncthreads();
    }

    const int rbase = i0 + warp_m*64 + (lid >> 2);
    const int cbase = j0 + warp_n*32 + (lid & 3)*2;
    #pragma unroll
    for (int mt = 0; mt < 4; mt++)
        #pragma unroll
        for (int nt = 0; nt < 4; nt++) {
            int row = rbase + mt*16;
            int col = cbase + nt*8;
            *(float2*)(C + (long)row*Nn + col)       = make_float2(acc[mt][nt][0], acc[mt][nt][1]);
            *(float2*)(C + (long)(row+8)*Nn + col)   = make_float2(acc[mt][nt][2], acc[mt][nt][3]);
        }
}

// ---------------------------------------------------------------------------
// K3 (tensorized): O = Va @ Wo + bo ; out = sigmoid(O[:128]) * O[128:].
// CTA = 128 rows (same (b,i)), 256 threads (8 warps x 16 rows). K=16, one
// k-step, bf16 split (3 products). Two half-passes hc: cols hc*64..+63 paired
// with +128 (gate/linear) in-register.
// ---------------------------------------------------------------------------
#define K3_OFF_AH 0          // 128*48 = 6144
#define K3_OFF_AL 6144
#define K3_OFF_BH 12288      // 256*48 = 12288
#define K3_OFF_BL 24576
#define K3_OFF_BO 36864      // 256*4
#define K3_SMEM   37888

__global__ __launch_bounds__(256) void k3_outproj(
    const float* __restrict__ Wo,
    const float* __restrict__ bo,
    float* __restrict__ out)
{
    extern __shared__ char smraw[];
    unsigned short* sAh = (unsigned short*)(smraw + K3_OFF_AH);  // [128][24]
    unsigned short* sAl = (unsigned short*)(smraw + K3_OFF_AL);
    unsigned short* sBh = (unsigned short*)(smraw + K3_OFF_BH);  // [256][24]
    unsigned short* sBl = (unsigned short*)(smraw + K3_OFF_BL);
    float*          sBo = (float*)(smraw + K3_OFF_BO);

    const int t   = threadIdx.x;
    const int wid = t >> 5, lid = t & 31;
    const long g0 = (long)blockIdx.x * 128;   // row base in (b,i,j) flattening
    const int b  = (int)(blockIdx.x >> 11);
    const int i  = (int)((blockIdx.x >> 2) & 511);
    const int j0 = (int)((blockIdx.x & 3) * 128);

    if (t < 256) sBo[t] = bo[t];
    // Wo^T split: sB[n][s]
    for (int idx = t; idx < 4096; idx += 256) {
        int s = idx >> 8, n = idx & 255;
        unsigned short h, l; split2(Wo[s*256 + n], h, l);
        sBh[n*24 + s] = h;
        sBl[n*24 + s] = l;
    }
    // Va tile: [128 j][16 s], split
    for (int it = 0; it < 2; it++) {
        int idx = it*256 + t;
        int s = idx >> 5, jc = idx & 31;
        float4 v = *(const float4*)(g_Va + (long)(b*16 + s)*NN + (long)i*Nn + j0 + jc*4);
        unsigned short h, l;
        split2(v.x, h, l); sAh[(jc*4+0)*24 + s] = h; sAl[(jc*4+0)*24 + s] = l;
        split2(v.y, h, l); sAh[(jc*4+1)*24 + s] = h; sAl[(jc*4+1)*24 + s] = l;
        split2(v.z, h, l); sAh[(jc*4+2)*24 + s] = h; sAl[(jc*4+2)*24 + s] = l;
        split2(v.w, h, l); sAh[(jc*4+3)*24 + s] = h; sAl[(jc*4+3)*24 + s] = l;
    }
    __syncthreads();

    const uint32_t sbAh = smem_u32(sAh);
    const uint32_t sbAl = smem_u32(sAl);
    const uint32_t sbBh = smem_u32(sBh);
    const uint32_t sbBl = smem_u32(sBl);
    const int lrow_a = (lid & 7) + ((lid >> 3) & 1) * 8;
    const int lk_a   = (lid >> 4) * 8;
    const int lrow_b = lid & 7;
    const int lk_b   = ((lid >> 3) & 1) * 8;

    // A fragments: rows 16*wid..+15, k 0..15 (single k-step)
    uint32_t ah[4], al[4];
    {
        uint32_t aoff = (uint32_t)((wid*16 + lrow_a)*48 + lk_a*2);
        ldsm_x4(ah[0], ah[1], ah[2], ah[3], sbAh + aoff);
        ldsm_x4(al[0], al[1], al[2], al[3], sbAl + aoff);
    }

    #pragma unroll
    for (int hc = 0; hc < 2; hc++) {
        float acc[2][8][4];
        #pragma unroll
        for (int gl = 0; gl < 2; gl++)
            #pragma unroll
            for (int nt = 0; nt < 8; nt++)
                #pragma unroll
                for (int q = 0; q < 4; q++) acc[gl][nt][q] = 0.f;

        #pragma unroll
        for (int gl = 0; gl < 2; gl++)
            #pragma unroll
            for (int nt = 0; nt < 8; nt++) {
                int nb = gl*128 + hc*64 + nt*8;
                uint32_t bh[2], bl[2];
                uint32_t boff = (uint32_t)((nb + lrow_b)*48 + lk_b*2);
                ldsm_x2(bh[0], bh[1], sbBh + boff);
                ldsm_x2(bl[0], bl[1], sbBl + boff);
                mma_bf16(acc[gl][nt], ah, bh);
                mma_bf16(acc[gl][nt], ah, bl);
                mma_bf16(acc[gl][nt], al, bh);
            }

        // Epilogue: row = 16*wid + (lid>>2) + rh*8, col = hc*64 + nt*8 + (lid&3)*2
        #pragma unroll
        for (int nt = 0; nt < 8; nt++)
            #pragma unroll
            for (int rh = 0; rh < 2; rh++) {
                int row = 16*wid + (lid >> 2) + rh*8;
                int c0  = hc*64 + nt*8 + (lid & 3)*2;
                float og0 = acc[0][nt][rh*2+0] + sBo[c0];
                float og1 = acc[0][nt][rh*2+1] + sBo[c0+1];
                float ol0 = acc[1][nt][rh*2+0] + sBo[c0+128];
                float ol1 = acc[1][nt][rh*2+1] + sBo[c0+129];
                *(float2*)(out + (g0 + row)*128 + c0) =
                    make_float2(sigmoidf_(og0)*ol0, sigmoidf_(og1)*ol1);
            }
    }
}

// ---------------------------------------------------------------------------
extern "C" void kernel_launch(void* const* d_in, const int* in_sizes, int n_in,
                              void* d_out, int out_size)
{
    const float* e    = (const float*)d_in[0];
    const float* mask = (const float*)d_in[1];
    const float* lnw  = (const float*)d_in[2];
    const float* lnb  = (const float*)d_in[3];
    const float* Wv   = (const float*)d_in[4];
    const float* bv   = (const float*)d_in[5];
    const float* We   = (const float*)d_in[6];
    const float* be   = (const float*)d_in[7];
    const float* Wo   = (const float*)d_in[8];
    const float* bo   = (const float*)d_in[9];
    float* out = (float*)d_out;

    static float* s_va = nullptr;
    if (!s_va) cudaGetSymbolAddress((void**)&s_va, g_Va);

    cudaFuncSetAttribute(k1_ln_proj_gate,
                         cudaFuncAttributeMaxDynamicSharedMemorySize, K1_SMEM);
    cudaFuncSetAttribute(k2_mma,
                         cudaFuncAttributeMaxDynamicSharedMemorySize, K2_SMEM);

    k1_ln_proj_gate<<<4096, 256, K1_SMEM>>>(e, mask, lnw, lnb, Wv, bv, We, be);

    dim3 gt(16, 16, 32);
    k_transpose<<<gt, dim3(32, 8)>>>();

    dim3 g2(4, 4, 32);
    k2_mma<<<g2, 256, K2_SMEM>>>(s_va);

    dim3 g3(4096);
    k3_outproj<<<g3, 256, K3_SMEM>>>(Wo, bo, out);
}

// round 11
// speedup vs baseline: 1.9616x; 1.4529x over previous
#include <cuda_runtime.h>
#include <cuda_bf16.h>
#include <cstdint>
#include <math.h>

#define Bb 2
#define Nn 512
#define Cc 128
#define Hh 8
#define NN (Nn*Nn)

// ---------------------------------------------------------------------------
// Scratch (no cudaMalloc): __device__ globals, all plain fp32 (tf32-rounded).
// g_P: 4 tensors x 16 planes (b*8+h) x [512][512]:
//   tensor 0 = V_in [i][k], 1 = V_out [k][j], 2 = E_in [i][k], 3 = E_out [k][i]
// g_PT: transposed out-planes: z<16 EoutT [i][k], z>=16 VoutT [j][k]
// ---------------------------------------------------------------------------
__device__ float    g_P [4*16*NN];
__device__ float    g_PT[32*NN];
__device__ float    g_Va[32*NN];        // [b][16 s][i][j], s: 0-7 in, 8-15 out
__device__ float    g_WtVE[64*128];     // [n][k] tf32, n: Vg,Vl,Vog,Vol,Eg,El,Eog,Eol
__device__ float    g_WoT [256*16];     // [n][s] tf32

__device__ __forceinline__ float sigmoidf_(float x){ return 1.0f/(1.0f + __expf(-x)); }

__device__ __forceinline__ uint32_t smem_u32(const void* p) {
    uint32_t a;
    asm("{ .reg .u64 t; cvta.to.shared.u64 t, %1; cvt.u32.u64 %0, t; }" : "=r"(a) : "l"(p));
    return a;
}
__device__ __forceinline__ float f2tf32(float f) {
    uint32_t r;
    asm("cvt.rna.tf32.f32 %0, %1;" : "=r"(r) : "f"(f));
    return __uint_as_float(r);
}
__device__ __forceinline__ void mma_tf32(float* c, const uint32_t* a, const uint32_t* b) {
    asm volatile("mma.sync.aligned.m16n8k8.row.col.f32.tf32.tf32.f32 "
        "{%0,%1,%2,%3}, {%4,%5,%6,%7}, {%8,%9}, {%0,%1,%2,%3};"
        : "+f"(c[0]), "+f"(c[1]), "+f"(c[2]), "+f"(c[3])
        : "r"(a[0]), "r"(a[1]), "r"(a[2]), "r"(a[3]), "r"(b[0]), "r"(b[1]));
}
__device__ __forceinline__ void cpasync16(uint32_t dst, const void* src) {
    asm volatile("cp.async.cg.shared.global [%0], [%1], 16;" :: "r"(dst), "l"(src));
}
#define CP_COMMIT() asm volatile("cp.async.commit_group;" ::: "memory")
#define CP_WAIT0()  asm volatile("cp.async.wait_group 0;" ::: "memory")
#define CP_WAIT1()  asm volatile("cp.async.wait_group 1;" ::: "memory")

// ---------------------------------------------------------------------------
// K0: weight prep (one block). Round Wv/We/Wo to tf32 into GEMM-ready layouts.
// ---------------------------------------------------------------------------
__global__ void k0_prep(const float* __restrict__ Wv, const float* __restrict__ We,
                        const float* __restrict__ Wo)
{
    const int t = threadIdx.x;
    for (int idx = t; idx < 8192; idx += 256) {
        int k = idx >> 6, n = idx & 63;
        float w = (n < 32) ? Wv[k*32 + n] : We[k*32 + (n - 32)];
        g_WtVE[n*128 + k] = f2tf32(w);
    }
    for (int idx = t; idx < 4096; idx += 256) {
        int s = idx >> 8, n = idx & 255;
        g_WoT[n*16 + s] = f2tf32(Wo[s*256 + n]);
    }
}

// ---------------------------------------------------------------------------
// K1: LN + dual projection (tf32 MMA, M=128 N=64 K=128) + gating.
// CTA = 128 rows (one (b,x), y0..y0+127), 256 threads (8 warps x 16 rows).
// Stores staged through SMEM for fully coalesced 512B plane segments.
// ---------------------------------------------------------------------------
#define K1_OFF_E    0             // 128*132*4 = 67584 (A tile, in-place LN+tf32)
#define K1_OFF_W    67584         // 64*132*4  = 33792 (reused as sOut after MMA)
#define K1_OFF_BIAS 101376        // 64*4
#define K1_OFF_MASK 101632        // 128*4
#define K1_OFF_PS   102144        // 256*4
#define K1_OFF_PQ   103168        // 256*4
#define K1_OFF_MU   104192        // 128*4
#define K1_OFF_RS   104704        // 128*4
#define K1_OFF_LNW  105216        // 128*4
#define K1_OFF_LNB  105728        // 128*4
#define K1_SMEM     106240

__global__ __launch_bounds__(256) void k1_ln_proj_gate(
    const float* __restrict__ e,
    const float* __restrict__ mask,
    const float* __restrict__ ln_w,
    const float* __restrict__ ln_b,
    const float* __restrict__ bv,
    const float* __restrict__ be)
{
    extern __shared__ char smraw[];
    float* sE    = (float*)(smraw + K1_OFF_E);     // [128][132]
    float* sW    = (float*)(smraw + K1_OFF_W);     // [64][132]
    float* sBias = (float*)(smraw + K1_OFF_BIAS);
    float* sMask = (float*)(smraw + K1_OFF_MASK);
    float* sPs   = (float*)(smraw + K1_OFF_PS);
    float* sPq   = (float*)(smraw + K1_OFF_PQ);
    float* sMu   = (float*)(smraw + K1_OFF_MU);
    float* sRs   = (float*)(smraw + K1_OFF_RS);
    float* sLnW  = (float*)(smraw + K1_OFF_LNW);
    float* sLnB  = (float*)(smraw + K1_OFF_LNB);

    const int t   = threadIdx.x;
    const int wid = t >> 5, lid = t & 31;
    const long g0 = (long)blockIdx.x * 128;
    const int b  = (int)(blockIdx.x >> 11);
    const int x  = (int)((blockIdx.x >> 2) & 511);
    const int y0 = (int)((blockIdx.x & 3) * 128);

    // Stage weights (pre-tf32), params.
    for (int idx = t; idx < 8192; idx += 256) {
        int n = idx >> 7, k = idx & 127;
        sW[n*132 + k] = g_WtVE[idx];
    }
    if (t < 64)  sBias[t] = (t < 32) ? bv[t] : be[t - 32];
    if (t < 128) { sLnW[t] = ln_w[t]; sLnB[t] = ln_b[t]; sMask[t] = mask[g0 + t]; }

    // Stage e tile [128][128].
    for (int it = 0; it < 16; it++) {
        int idx = it*256 + t;
        int row = idx >> 5, c4 = idx & 31;
        float4 v = *(const float4*)(e + (g0 + row)*Cc + c4*4);
        *(float4*)(sE + row*132 + c4*4) = v;
    }
    __syncthreads();

    // LN stats: 2 threads per row.
    {
        int row = t >> 1, half = t & 1;
        float s = 0.f, q = 0.f;
        const float* p = sE + row*132 + half*64;
        #pragma unroll 8
        for (int c = 0; c < 64; c++) { float v = p[c]; s += v; q += v*v; }
        sPs[t] = s; sPq[t] = q;
    }
    __syncthreads();
    if (t < 128) {
        float s = sPs[t*2] + sPs[t*2+1];
        float q = sPq[t*2] + sPq[t*2+1];
        float mu  = s * (1.f/128.f);
        float var = q * (1.f/128.f) - mu*mu;
        sMu[t] = mu;
        sRs[t] = rsqrtf(var + 1e-5f);
    }
    __syncthreads();

    // Normalize + tf32-round in place (sE becomes the A tile).
    {
        int row = t >> 1, half = t & 1;
        float mu = sMu[row], rs = sRs[row];
        #pragma unroll 4
        for (int c = half*64; c < half*64 + 64; c++) {
            float v = (sE[row*132 + c] - mu) * rs * sLnW[c] + sLnB[c];
            sE[row*132 + c] = f2tf32(v);
        }
    }
    __syncthreads();

    // MMA: warp wid owns rows 16*wid..+15; N=64 (8 nt); K=128 (16 k-steps).
    const uint32_t* uE = (const uint32_t*)sE;
    const uint32_t* uW = (const uint32_t*)sW;
    const int r0 = wid*16 + (lid >> 2);
    const int kc = lid & 3;

    float acc[8][4];
    #pragma unroll
    for (int nt = 0; nt < 8; nt++)
        #pragma unroll
        for (int q = 0; q < 4; q++) acc[nt][q] = 0.f;

    #pragma unroll
    for (int ks = 0; ks < 16; ks++) {
        uint32_t a[4];
        a[0] = uE[(r0    )*132 + ks*8 + kc];
        a[1] = uE[(r0 + 8)*132 + ks*8 + kc];
        a[2] = uE[(r0    )*132 + ks*8 + kc + 4];
        a[3] = uE[(r0 + 8)*132 + ks*8 + kc + 4];
        #pragma unroll
        for (int nt = 0; nt < 8; nt++) {
            uint32_t bfr[2];
            int n0 = nt*8 + (lid >> 2);
            bfr[0] = uW[n0*132 + ks*8 + kc];
            bfr[1] = uW[n0*132 + ks*8 + kc + 4];
            mma_tf32(acc[nt], a, bfr);
        }
    }
    __syncthreads();   // all warps done with sW; reuse as sOut

    // Gate -> sOut[tensor][h][row] (tensor 0=Vin,1=Vout,2=Ein,3=Eout).
    float* sOut = sW;
    #pragma unroll
    for (int q = 0; q < 4; q++) {
        int row = 16*wid + (lid >> 2) + ((q >> 1) * 8);
        int h   = (lid & 3)*2 + (q & 1);
        float m = sMask[row];
        float vin  = sigmoidf_(acc[0][q] + sBias[h]      + m) * (acc[1][q] + sBias[8  + h]);
        float vout = sigmoidf_(acc[2][q] + sBias[16 + h] + m) * (acc[3][q] + sBias[24 + h]);
        float ein  = sigmoidf_(acc[4][q] + sBias[32 + h] + m) * (acc[5][q] + sBias[40 + h]);
        float eout = sigmoidf_(acc[6][q] + sBias[48 + h] + m) * (acc[7][q] + sBias[56 + h]);
        sOut[(0*8 + h)*128 + row] = f2tf32(vin);
        sOut[(1*8 + h)*128 + row] = f2tf32(vout);
        sOut[(2*8 + h)*128 + row] = f2tf32(ein);
        sOut[(3*8 + h)*128 + row] = f2tf32(eout);
    }
    __syncthreads();

    // Coalesced copy out: 32 segments of 128 floats; 8 threads per segment.
    {
        int seg = t >> 3;             // 0..31 = tensor*8 + h
        int sub = t & 7;              // 16 floats each
        int tensor = seg >> 3, h = seg & 7;
        float* dst = g_P + ((long)(tensor*16 + b*8 + h)*NN) + (long)x*Nn + y0 + sub*16;
        const float* src = sOut + seg*128 + sub*16;
        #pragma unroll
        for (int q = 0; q < 4; q++)
            *(float4*)(dst + q*4) = *(const float4*)(src + q*4);
    }
}

// ---------------------------------------------------------------------------
// Transpose 512x512 fp32 planes: Eout (tensor 3) and Vout (tensor 1) -> g_PT.
// ---------------------------------------------------------------------------
__global__ __launch_bounds__(256) void k_transpose()
{
    __shared__ float tl[32][33];
    const int z = blockIdx.z;
    const float* src = (z < 16) ? (g_P + (long)(3*16 + z)*NN)
                                : (g_P + (long)(1*16 + (z-16))*NN);
    float* dst = g_PT + (long)z*NN;
    const int x0 = blockIdx.x * 32;
    const int y0 = blockIdx.y * 32;
    const int tx = threadIdx.x, ty = threadIdx.y;
    #pragma unroll
    for (int rr = 0; rr < 32; rr += 8)
        tl[ty + rr][tx] = src[(long)(x0 + ty + rr)*Nn + y0 + tx];
    __syncthreads();
    #pragma unroll
    for (int rr = 0; rr < 32; rr += 8)
        dst[(long)(y0 + ty + rr)*Nn + x0 + tx] = tl[tx][ty + rr];
}

// ---------------------------------------------------------------------------
// K2: tf32 GEMM, CTA tile 128x128, K-chunk 64, cp.async double-buffered.
// 8 warps = 2(m) x 4(n), warp tile 64x32. D[i,j] = sum_k A[i,k]*B[j,k].
// grid (4,4,32): z<16 "in" planes; z>=16 "out" (transposed) planes.
// ---------------------------------------------------------------------------
#define K2_STRF  68
#define K2_TILEF (128*K2_STRF)
#define K2_BUFF  (2*K2_TILEF)
#define K2_SMEMB (2*K2_BUFF*4)   // 139264 B

__global__ __launch_bounds__(256, 1) void k2_mma(float* __restrict__ Va)
{
    extern __shared__ float sm2[];
    const uint32_t sb2 = smem_u32(sm2);
    const int t = threadIdx.x;
    const int wid = t >> 5, lid = t & 31;
    const int warp_m = wid >> 2;
    const int warp_n = wid & 3;

    const int z = blockIdx.z;
    const float* A;
    const float* B;
    float* C;
    if (z < 16) {
        A = g_P + (long)(2*16 + z)*NN;      // E_in [i][k]
        B = g_P + (long)z*NN;               // V_in [j][k]
        C = Va + (long)((z >> 3)*16 + (z & 7))*NN;
    } else {
        int p = z - 16;
        A = g_PT + (long)p*NN;              // EoutT [i][k]
        B = g_PT + (long)(16 + p)*NN;       // VoutT [j][k]
        C = Va + (long)((p >> 3)*16 + 8 + (p & 7))*NN;
    }
    const int i0 = blockIdx.y * 128;
    const int j0 = blockIdx.x * 128;

    const int r0k = lid >> 2;
    const int kc4 = lid & 3;

    float acc[4][4][4];
    #pragma unroll
    for (int mt = 0; mt < 4; mt++)
        #pragma unroll
        for (int nt = 0; nt < 4; nt++)
            #pragma unroll
            for (int q = 0; q < 4; q++) acc[mt][nt][q] = 0.f;

    // --- stage chunk kc into buffer buf ---
    #define K2_STAGE(kc, buf) do { \
        int _k0 = (kc) * 64; \
        _Pragma("unroll") \
        for (int it = 0; it < 16; it++) { \
            int idx = it*256 + t; \
            int half = idx >> 11; \
            int r = (idx >> 4) & 127; \
            int c = idx & 15; \
            const float* src = (half ? B + (long)(j0 + r)*Nn : A + (long)(i0 + r)*Nn) + _k0 + c*4; \
            uint32_t dst = sb2 + (uint32_t)(((buf)*K2_BUFF + half*K2_TILEF + r*K2_STRF + c*4)*4); \
            cpasync16(dst, src); \
        } \
        CP_COMMIT(); \
    } while (0)

    K2_STAGE(0, 0);

    for (int kc = 0; kc < 8; kc++) {
        if (kc < 7) { K2_STAGE(kc + 1, (kc + 1) & 1); CP_WAIT1(); }
        else        { CP_WAIT0(); }
        __syncthreads();

        const uint32_t* uA = (const uint32_t*)(sm2 + (kc & 1)*K2_BUFF);
        const uint32_t* uB = uA + K2_TILEF;

        #pragma unroll
        for (int ks = 0; ks < 8; ks++) {
            uint32_t a[4][4];
            #pragma unroll
            for (int mt = 0; mt < 4; mt++) {
                int r0 = warp_m*64 + mt*16 + r0k;
                a[mt][0] = uA[(r0    )*K2_STRF + ks*8 + kc4];
                a[mt][1] = uA[(r0 + 8)*K2_STRF + ks*8 + kc4];
                a[mt][2] = uA[(r0    )*K2_STRF + ks*8 + kc4 + 4];
                a[mt][3] = uA[(r0 + 8)*K2_STRF + ks*8 + kc4 + 4];
            }
            #pragma unroll
            for (int nt = 0; nt < 4; nt++) {
                uint32_t bfr[2];
                int n0 = warp_n*32 + nt*8 + r0k;
                bfr[0] = uB[n0*K2_STRF + ks*8 + kc4];
                bfr[1] = uB[n0*K2_STRF + ks*8 + kc4 + 4];
                #pragma unroll
                for (int mt = 0; mt < 4; mt++)
                    mma_tf32(acc[mt][nt], a[mt], bfr);
            }
        }
        __syncthreads();
    }

    const int rbase = i0 + warp_m*64 + (lid >> 2);
    const int cbase = j0 + warp_n*32 + (lid & 3)*2;
    #pragma unroll
    for (int mt = 0; mt < 4; mt++)
        #pragma unroll
        for (int nt = 0; nt < 4; nt++) {
            int row = rbase + mt*16;
            int col = cbase + nt*8;
            *(float2*)(C + (long)row*Nn + col)     = make_float2(acc[mt][nt][0], acc[mt][nt][1]);
            *(float2*)(C + (long)(row+8)*Nn + col) = make_float2(acc[mt][nt][2], acc[mt][nt][3]);
        }
}

// ---------------------------------------------------------------------------
// K3: O = Va @ Wo + bo ; out = sigmoid(O[:128]) * O[128:].
// CTA = one (b,i), all 512 j rows, 256 threads (8 warps x 64 rows).
// tf32 MMA, K=16 (2 k-steps), Wo pre-rounded; inline epilogue per col group.
// ---------------------------------------------------------------------------
#define K3_OFF_VA 0              // 512*20*4 = 40960
#define K3_OFF_WO 40960          // 256*20*4 = 20480
#define K3_OFF_BO 61440          // 256*4
#define K3_SMEM   62464

__global__ __launch_bounds__(256) void k3_outproj(
    const float* __restrict__ bo,
    float* __restrict__ out)
{
    extern __shared__ char smraw[];
    float* sVa = (float*)(smraw + K3_OFF_VA);   // [512][20]
    float* sWo = (float*)(smraw + K3_OFF_WO);   // [256][20]
    float* sBo = (float*)(smraw + K3_OFF_BO);

    const int t   = threadIdx.x;
    const int wid = t >> 5, lid = t & 31;
    const int i = blockIdx.x;
    const int b = blockIdx.y;

    if (t < 256) sBo[t] = bo[t];
    for (int idx = t; idx < 4096; idx += 256) {
        int n = idx >> 4, s = idx & 15;
        sWo[n*20 + s] = g_WoT[idx];
    }
    for (int it = 0; it < 32; it++) {
        int idx = it*256 + t;
        int s = idx >> 9, j = idx & 511;
        sVa[j*20 + s] = f2tf32(g_Va[(long)(b*16 + s)*NN + (long)i*Nn + j]);
    }
    __syncthreads();

    const uint32_t* uVa = (const uint32_t*)sVa;
    const uint32_t* uWo = (const uint32_t*)sWo;
    const int rk = lid >> 2;
    const int kc = lid & 3;

    // A fragments: 4 m-tiles x 2 k-steps, hoisted.
    uint32_t a[4][2][4];
    #pragma unroll
    for (int mt = 0; mt < 4; mt++) {
        int r0 = wid*64 + mt*16 + rk;
        #pragma unroll
        for (int ks = 0; ks < 2; ks++) {
            a[mt][ks][0] = uVa[(r0    )*20 + ks*8 + kc];
            a[mt][ks][1] = uVa[(r0 + 8)*20 + ks*8 + kc];
            a[mt][ks][2] = uVa[(r0    )*20 + ks*8 + kc + 4];
            a[mt][ks][3] = uVa[(r0 + 8)*20 + ks*8 + kc + 4];
        }
    }

    float* obase = out + ((long)(b*Nn + i)*Nn) * 128;

    #pragma unroll 4
    for (int cg = 0; cg < 16; cg++) {
        uint32_t bg[2][2], bl[2][2];
        #pragma unroll
        for (int ks = 0; ks < 2; ks++) {
            int ng = cg*8 + rk;
            bg[ks][0] = uWo[(ng      )*20 + ks*8 + kc];
            bg[ks][1] = uWo[(ng      )*20 + ks*8 + kc + 4];
            bl[ks][0] = uWo[(ng + 128)*20 + ks*8 + kc];
            bl[ks][1] = uWo[(ng + 128)*20 + ks*8 + kc + 4];
        }
        float ag[4][4], al[4][4];
        #pragma unroll
        for (int mt = 0; mt < 4; mt++)
            #pragma unroll
            for (int q = 0; q < 4; q++) { ag[mt][q] = 0.f; al[mt][q] = 0.f; }
        #pragma unroll
        for (int ks = 0; ks < 2; ks++)
            #pragma unroll
            for (int mt = 0; mt < 4; mt++) {
                mma_tf32(ag[mt], a[mt][ks], bg[ks]);
                mma_tf32(al[mt], a[mt][ks], bl[ks]);
            }
        int c0 = cg*8 + (lid & 3)*2;
        float bg0 = sBo[c0], bg1 = sBo[c0+1], bl0 = sBo[c0+128], bl1 = sBo[c0+129];
        #pragma unroll
        for (int mt = 0; mt < 4; mt++) {
            int r = wid*64 + mt*16 + (lid >> 2);
            *(float2*)(obase + (long)r*128 + c0) = make_float2(
                sigmoidf_(ag[mt][0] + bg0) * (al[mt][0] + bl0),
                sigmoidf_(ag[mt][1] + bg1) * (al[mt][1] + bl1));
            *(float2*)(obase + (long)(r+8)*128 + c0) = make_float2(
                sigmoidf_(ag[mt][2] + bg0) * (al[mt][2] + bl0),
                sigmoidf_(ag[mt][3] + bg1) * (al[mt][3] + bl1));
        }
    }
}

// ---------------------------------------------------------------------------
extern "C" void kernel_launch(void* const* d_in, const int* in_sizes, int n_in,
                              void* d_out, int out_size)
{
    const float* e    = (const float*)d_in[0];
    const float* mask = (const float*)d_in[1];
    const float* lnw  = (const float*)d_in[2];
    const float* lnb  = (const float*)d_in[3];
    const float* Wv   = (const float*)d_in[4];
    const float* bv   = (const float*)d_in[5];
    const float* We   = (const float*)d_in[6];
    const float* be   = (const float*)d_in[7];
    const float* Wo   = (const float*)d_in[8];
    const float* bo   = (const float*)d_in[9];
    float* out = (float*)d_out;

    static float* s_va = nullptr;
    if (!s_va) cudaGetSymbolAddress((void**)&s_va, g_Va);

    cudaFuncSetAttribute(k1_ln_proj_gate,
                         cudaFuncAttributeMaxDynamicSharedMemorySize, K1_SMEM);
    cudaFuncSetAttribute(k2_mma,
                         cudaFuncAttributeMaxDynamicSharedMemorySize, K2_SMEMB);
    cudaFuncSetAttribute(k3_outproj,
                         cudaFuncAttributeMaxDynamicSharedMemorySize, K3_SMEM);

    k0_prep<<<1, 256>>>(Wv, We, Wo);

    k1_ln_proj_gate<<<4096, 256, K1_SMEM>>>(e, mask, lnw, lnb, bv, be);

    dim3 gt(16, 16, 32);
    k_transpose<<<gt, dim3(32, 8)>>>();

    dim3 g2(4, 4, 32);
    k2_mma<<<g2, 256, K2_SMEMB>>>(s_va);

    dim3 g3(Nn, Bb);
    k3_outproj<<<g3, 256, K3_SMEM>>>(bo, out);
}